// round 17
// baseline (speedup 1.0000x reference)
#include <cuda_runtime.h>
#include <cuda_bf16.h>
#include <math.h>

#define BN      8192        // B*N nodes
#define E_TOT   262144      // edges
#define HID     128
#define NRBF    64
#define NBLK    4
#define P_TAB   256         // edge-filter lookup table resolution

static __device__ float g_h   [BN * HID];
static __device__ short g_hlq [BN * HID];   // int16 row-quantized hl
static __device__ float g_hls [BN];         // per-row scale for hl
static __device__ float g_agg [BN * HID];
static __device__ float g_tmp [BN * HID];
static __device__ float g_x   [BN * 64];
static __device__ float g_d   [E_TOT];
static __device__ int2  g_e2  [E_TOT];      // {src, bitcast(d)} per CSR slot
static __device__ int   g_deg [BN];
static __device__ int   g_off [BN + 1];
static __device__ int   g_cur [BN];
static __device__ int   g_part[32];
static __device__ int   g_base[32];
static __device__ float g_htab[NBLK * P_TAB * HID];
static __device__ float g_tab [NBLK * P_TAB * HID];

__device__ __forceinline__ float silu_f(float v) {
    return v / (1.0f + __expf(-v));
}

__device__ __forceinline__ unsigned f2tf32(float f) {
    unsigned u;
    asm("cvt.rna.tf32.f32 %0, %1;" : "=r"(u) : "f"(f));
    return u;
}

__device__ __forceinline__ void mma8(float* c, unsigned a0, unsigned a1,
                                     unsigned a2, unsigned a3,
                                     unsigned b0, unsigned b1) {
    asm("mma.sync.aligned.m16n8k8.row.col.f32.tf32.tf32.f32 "
        "{%0,%1,%2,%3},{%4,%5,%6,%7},{%8,%9},{%0,%1,%2,%3};"
        : "+f"(c[0]), "+f"(c[1]), "+f"(c[2]), "+f"(c[3])
        : "r"(a0), "r"(a1), "r"(a2), "r"(a3), "r"(b0), "r"(b1));
}

// load W fragments for warp wi's 16 output cols into bw[64]
__device__ __forceinline__ void load_w64(unsigned* bw, const float* __restrict__ W,
                                         int wi, int lane) {
    int bc = wi * 16 + (lane >> 2);
    int br = lane & 3;
#pragma unroll
    for (int ks = 0; ks < 16; ks++) {
#pragma unroll
        for (int nt = 0; nt < 2; nt++) {
            bw[ks * 4 + nt * 2 + 0] = f2tf32(__ldg(&W[(ks * 8 + br) * HID + bc + nt * 8]));
            bw[ks * 4 + nt * 2 + 1] = f2tf32(__ldg(&W[(ks * 8 + br + 4) * HID + bc + nt * 8]));
        }
    }
}

// interleaved dual-tile mma pass: tiles ms=mp*2 and ms=mp*2+1.
__device__ __forceinline__ void mma_pair(
    const float* sA, const unsigned* bw, int mp, int g, int tg,
    float* cA0, float* cA1, float* cB0, float* cB1)
{
#pragma unroll
    for (int ks = 0; ks < 16; ks++) {
        int rA = (mp * 2) * 16 + g;
        int rB = rA + 16;
        int cc = ks * 8 + tg;
        unsigned a0 = __float_as_uint(sA[rA * 132 + cc]);
        unsigned a1 = __float_as_uint(sA[(rA + 8) * 132 + cc]);
        unsigned a2 = __float_as_uint(sA[rA * 132 + cc + 4]);
        unsigned a3 = __float_as_uint(sA[(rA + 8) * 132 + cc + 4]);
        unsigned b0 = __float_as_uint(sA[rB * 132 + cc]);
        unsigned b1 = __float_as_uint(sA[(rB + 8) * 132 + cc]);
        unsigned b2 = __float_as_uint(sA[rB * 132 + cc + 4]);
        unsigned b3 = __float_as_uint(sA[(rB + 8) * 132 + cc + 4]);
        mma8(cA0, a0, a1, a2, a3, bw[ks * 4 + 0], bw[ks * 4 + 1]);
        mma8(cB0, b0, b1, b2, b3, bw[ks * 4 + 0], bw[ks * 4 + 1]);
        mma8(cA1, a0, a1, a2, a3, bw[ks * 4 + 2], bw[ks * 4 + 3]);
        mma8(cB1, b0, b1, b2, b3, bw[ks * 4 + 2], bw[ks * 4 + 3]);
    }
}

// quantize one 128-col row held as float4-per-lane: absmax-scale to int16
__device__ __forceinline__ void quant_row(float4 v, long grow, int lane) {
    float am = fmaxf(fmaxf(fabsf(v.x), fabsf(v.y)), fmaxf(fabsf(v.z), fabsf(v.w)));
#pragma unroll
    for (int o = 16; o > 0; o >>= 1)
        am = fmaxf(am, __shfl_xor_sync(0xffffffffu, am, o));
    am = fmaxf(am, 1e-20f);
    float inv = 32767.0f / am;
    short4 q;
    q.x = (short)__float2int_rn(v.x * inv);
    q.y = (short)__float2int_rn(v.y * inv);
    q.z = (short)__float2int_rn(v.z * inv);
    q.w = (short)__float2int_rn(v.w * inv);
    *(short4*)&g_hlq[grow * HID + lane * 4] = q;
    if (lane == 0) g_hls[grow] = am * (1.0f / 32767.0f);
}

// ---------------------------------------------------------------------------
// Setup kernels
// ---------------------------------------------------------------------------

__global__ void k_embed(const int* __restrict__ Z, const float* __restrict__ ew) {
    int idx = blockIdx.x * blockDim.x + threadIdx.x;   // BN*HID
    int n = idx >> 7, c = idx & 127;
    g_h[idx] = ew[Z[n] * HID + c];
    if (idx < BN) g_deg[idx] = 0;   // fused deg zeroing (ordered before k_dist_hist)
}

__global__ void k_dist_hist(const int* __restrict__ ei, const float* __restrict__ pos) {
    int e = blockIdx.x * blockDim.x + threadIdx.x;
    if (e >= E_TOT) return;
    int s = ei[e];
    int t = ei[E_TOT + e];
    float dx = pos[s * 3 + 0] - pos[t * 3 + 0];
    float dy = pos[s * 3 + 1] - pos[t * 3 + 1];
    float dz = pos[s * 3 + 2] - pos[t * 3 + 2];
    float d = sqrtf(fmaf(dx, dx, fmaf(dy, dy, dz * dz)));
    d = fminf(d, 6.0f);
    g_d[e] = d;
    atomicAdd(&g_deg[t], 1);
}

// hierarchical scan: 32 blocks x 256 threads -> per-block exclusive offsets
__global__ void __launch_bounds__(256) k_scan1() {
    __shared__ int sw[8];
    int b = blockIdx.x, t = threadIdx.x, wid = t >> 5, lane = t & 31;
    int i = b * 256 + t;
    int v = g_deg[i];
    int incl = v;
#pragma unroll
    for (int o = 1; o < 32; o <<= 1) {
        int x = __shfl_up_sync(0xffffffffu, incl, o);
        if (lane >= o) incl += x;
    }
    if (lane == 31) sw[wid] = incl;
    __syncthreads();
    int wb = 0;
#pragma unroll
    for (int w = 0; w < 8; w++)
        if (w < wid) wb += sw[w];
    g_off[i] = wb + incl - v;
    if (t == 255) g_part[b] = wb + incl;
}

__global__ void k_scan2() {
    int lane = threadIdx.x;
    int v = g_part[lane];
    int incl = v;
#pragma unroll
    for (int o = 1; o < 32; o <<= 1) {
        int x = __shfl_up_sync(0xffffffffu, incl, o);
        if (lane >= o) incl += x;
    }
    g_base[lane] = incl - v;
    if (lane == 31) g_off[BN] = incl;
}

__global__ void __launch_bounds__(256) k_scan3() {
    int b = blockIdx.x, t = threadIdx.x;
    int i = b * 256 + t;
    int o = g_off[i] + g_base[b];
    g_off[i] = o;
    g_cur[i] = o;
}

__global__ void k_bucket(const int* __restrict__ ei) {
    int e = blockIdx.x * blockDim.x + threadIdx.x;
    if (e >= E_TOT) return;
    int t = ei[E_TOT + e];
    int p = atomicAdd(&g_cur[t], 1);
    g_e2[p] = make_int2(ei[e], __float_as_int(g_d[e]));
}

// ---------------------------------------------------------------------------
// tf32 MMA GEMM: 256 threads, 64 rows/block, grid=128; W in 64 regs/thread.
// EPI: 1 bias+silu -> O (float), 2 quant -> g_hlq/g_hls (int16 + row scale).
// ---------------------------------------------------------------------------

template <int EPI>
__global__ void __launch_bounds__(256) k_mma(
    const float* __restrict__ A, const float* __restrict__ W,
    const float* __restrict__ bias, float* __restrict__ O)
{
    __shared__ float sA[64 * 132];
    __shared__ float sC[16 * 132];
    int tid = threadIdx.x, warp = tid >> 5, lane = tid & 31;
    long row0 = (long)blockIdx.x * 64;

    {
        const float4* Ag = (const float4*)(A + row0 * HID);
#pragma unroll
        for (int i = 0; i < 8; i++) {
            int idx = tid + i * 256;
            int r = idx >> 5, c4 = idx & 31;
            float4 v = Ag[idx];
            v.x = __uint_as_float(f2tf32(v.x));
            v.y = __uint_as_float(f2tf32(v.y));
            v.z = __uint_as_float(f2tf32(v.z));
            v.w = __uint_as_float(f2tf32(v.w));
            *(float4*)&sA[r * 132 + c4 * 4] = v;
        }
    }

    unsigned bw[64];
    load_w64(bw, W, warp, lane);
    __syncthreads();

    int g = lane >> 2, tg = lane & 3;
    int cb0 = warp * 16 + tg * 2;
    int cb1 = cb0 + 8;

#pragma unroll
    for (int mp = 0; mp < 2; mp++) {
        float cA0[4] = {0.f, 0.f, 0.f, 0.f};
        float cA1[4] = {0.f, 0.f, 0.f, 0.f};
        float cB0[4] = {0.f, 0.f, 0.f, 0.f};
        float cB1[4] = {0.f, 0.f, 0.f, 0.f};
        mma_pair(sA, bw, mp, g, tg, cA0, cA1, cB0, cB1);

#pragma unroll
        for (int half = 0; half < 2; half++) {
            int ms = mp * 2 + half;
            const float* c0 = half ? cB0 : cA0;
            const float* c1 = half ? cB1 : cA1;
            *(float2*)&sC[g * 132 + cb0]       = make_float2(c0[0], c0[1]);
            *(float2*)&sC[(g + 8) * 132 + cb0] = make_float2(c0[2], c0[3]);
            *(float2*)&sC[g * 132 + cb1]       = make_float2(c1[0], c1[1]);
            *(float2*)&sC[(g + 8) * 132 + cb1] = make_float2(c1[2], c1[3]);
            __syncthreads();
            if (EPI == 1) {
#pragma unroll
                for (int j = 0; j < 2; j++) {
                    int idx = tid + j * 256;
                    int r = idx >> 5, c4 = idx & 31;
                    float4 v = *(float4*)&sC[r * 132 + c4 * 4];
                    float4 b = *(const float4*)&bias[c4 * 4];
                    v.x = silu_f(v.x + b.x);
                    v.y = silu_f(v.y + b.y);
                    v.z = silu_f(v.z + b.z);
                    v.w = silu_f(v.w + b.w);
                    *(float4*)&O[(row0 + ms * 16 + r) * HID + c4 * 4] = v;
                }
            } else {
                // int16 row quantization; each warp handles 2 rows
#pragma unroll
                for (int rh = 0; rh < 2; rh++) {
                    int r = warp * 2 + rh;
                    float4 v = *(float4*)&sC[r * 132 + lane * 4];
                    quant_row(v, row0 + ms * 16 + r, lane);
                }
            }
            __syncthreads();
        }
    }
}

// ---------------------------------------------------------------------------
// F2: node_w2 GEMM + bias + residual + layernorm -> h, then (SECOND) the
// NEXT block's lin_in GEMM on fresh h -> quantized hl (int16 + scales).
// ---------------------------------------------------------------------------

template <int SECOND>
__global__ void __launch_bounds__(256) k_f2(
    const float* __restrict__ A, const float* __restrict__ W2,
    const float* __restrict__ bias, float* __restrict__ H,
    const float* __restrict__ lng, const float* __restrict__ lnb,
    const float* __restrict__ Wn)
{
    __shared__ float sA[64 * 132];
    __shared__ float sC[16 * 132];
    int tid = threadIdx.x, warp = tid >> 5, lane = tid & 31;
    long row0 = (long)blockIdx.x * 64;

    {
        const float4* Ag = (const float4*)(A + row0 * HID);
#pragma unroll
        for (int i = 0; i < 8; i++) {
            int idx = tid + i * 256;
            int r = idx >> 5, c4 = idx & 31;
            float4 v = Ag[idx];
            v.x = __uint_as_float(f2tf32(v.x));
            v.y = __uint_as_float(f2tf32(v.y));
            v.z = __uint_as_float(f2tf32(v.z));
            v.w = __uint_as_float(f2tf32(v.w));
            *(float4*)&sA[r * 132 + c4 * 4] = v;
        }
    }

    unsigned bw[64];
    load_w64(bw, W2, warp, lane);
    __syncthreads();

    int g = lane >> 2, tg = lane & 3;
    int cb0 = warp * 16 + tg * 2;
    int cb1 = cb0 + 8;

#pragma unroll
    for (int mp = 0; mp < 2; mp++) {
        float cA0[4] = {0.f, 0.f, 0.f, 0.f};
        float cA1[4] = {0.f, 0.f, 0.f, 0.f};
        float cB0[4] = {0.f, 0.f, 0.f, 0.f};
        float cB1[4] = {0.f, 0.f, 0.f, 0.f};
        mma_pair(sA, bw, mp, g, tg, cA0, cA1, cB0, cB1);

#pragma unroll
        for (int half = 0; half < 2; half++) {
            int ms = mp * 2 + half;
            const float* c0 = half ? cB0 : cA0;
            const float* c1 = half ? cB1 : cA1;
            *(float2*)&sC[g * 132 + cb0]       = make_float2(c0[0], c0[1]);
            *(float2*)&sC[(g + 8) * 132 + cb0] = make_float2(c0[2], c0[3]);
            *(float2*)&sC[g * 132 + cb1]       = make_float2(c1[0], c1[1]);
            *(float2*)&sC[(g + 8) * 132 + cb1] = make_float2(c1[2], c1[3]);
            __syncthreads();

            // bias + residual + layernorm; each warp handles 2 rows
#pragma unroll
            for (int rh = 0; rh < 2; rh++) {
                int r = warp * 2 + rh;
                long grow = row0 + ms * 16 + r;
                float4 cv = *(float4*)&sC[r * 132 + lane * 4];
                float4 rv = *(const float4*)&H[grow * HID + lane * 4];
                float4 bvv = *(const float4*)&bias[lane * 4];
                float x0 = cv.x + rv.x + bvv.x;
                float x1 = cv.y + rv.y + bvv.y;
                float x2 = cv.z + rv.z + bvv.z;
                float x3 = cv.w + rv.w + bvv.w;
                float s = x0 + x1 + x2 + x3;
                float q = fmaf(x0, x0, fmaf(x1, x1, fmaf(x2, x2, x3 * x3)));
#pragma unroll
                for (int o = 16; o > 0; o >>= 1) {
                    s += __shfl_down_sync(0xffffffffu, s, o);
                    q += __shfl_down_sync(0xffffffffu, q, o);
                }
                s = __shfl_sync(0xffffffffu, s, 0);
                q = __shfl_sync(0xffffffffu, q, 0);
                float mu = s * (1.0f / HID);
                float rs = rsqrtf(q * (1.0f / HID) - mu * mu + 1e-5f);
                float4 gv = *(const float4*)&lng[lane * 4];
                float4 b2 = *(const float4*)&lnb[lane * 4];
                float4 ov;
                ov.x = (x0 - mu) * rs * gv.x + b2.x;
                ov.y = (x1 - mu) * rs * gv.y + b2.y;
                ov.z = (x2 - mu) * rs * gv.z + b2.z;
                ov.w = (x3 - mu) * rs * gv.w + b2.w;
                *(float4*)&H[grow * HID + lane * 4] = ov;
                if (SECOND) {
                    ov.x = __uint_as_float(f2tf32(ov.x));
                    ov.y = __uint_as_float(f2tf32(ov.y));
                    ov.z = __uint_as_float(f2tf32(ov.z));
                    ov.w = __uint_as_float(f2tf32(ov.w));
                    int sr = ms * 16 + r;
                    *(float4*)&sA[sr * 132 + lane * 4] = ov;
                }
            }
            __syncthreads();
        }
    }

    if (SECOND) {
        // second GEMM: hl = h_new @ Wn, output quantized to int16
        load_w64(bw, Wn, warp, lane);
#pragma unroll
        for (int mp = 0; mp < 2; mp++) {
            float cA0[4] = {0.f, 0.f, 0.f, 0.f};
            float cA1[4] = {0.f, 0.f, 0.f, 0.f};
            float cB0[4] = {0.f, 0.f, 0.f, 0.f};
            float cB1[4] = {0.f, 0.f, 0.f, 0.f};
            mma_pair(sA, bw, mp, g, tg, cA0, cA1, cB0, cB1);
#pragma unroll
            for (int half = 0; half < 2; half++) {
                int ms = mp * 2 + half;
                const float* c0 = half ? cB0 : cA0;
                const float* c1 = half ? cB1 : cA1;
                *(float2*)&sC[g * 132 + cb0]       = make_float2(c0[0], c0[1]);
                *(float2*)&sC[(g + 8) * 132 + cb0] = make_float2(c0[2], c0[3]);
                *(float2*)&sC[g * 132 + cb1]       = make_float2(c1[0], c1[1]);
                *(float2*)&sC[(g + 8) * 132 + cb1] = make_float2(c1[2], c1[3]);
                __syncthreads();
#pragma unroll
                for (int rh = 0; rh < 2; rh++) {
                    int r = warp * 2 + rh;
                    float4 v = *(float4*)&sC[r * 132 + lane * 4];
                    quant_row(v, row0 + ms * 16 + r, lane);
                }
                __syncthreads();
            }
        }
    }
}

// ---------------------------------------------------------------------------
// fp32 GEMM (table GEMMs + readout). R=16 rows/block.
// GEN=1: A is generated on the fly as RBF features (ignores A pointer).
// ---------------------------------------------------------------------------

template <int K, int N, int EPI, int PREACT, int GEN>
__global__ void __launch_bounds__(N) k_gemm(
    const float* __restrict__ A, const float* __restrict__ W,
    const float* __restrict__ bias, float* __restrict__ O,
    long aStrideY, long wStrideY, long bStrideY, long oStrideY)
{
    constexpr int R = 16;
    __shared__ float sA[R * K];

    int t = threadIdx.x;
    int y = blockIdx.y;
    long row0 = (long)blockIdx.x * R;

    const float* Ab = A + y * aStrideY + row0 * K;
    const float* Wb = W + y * wStrideY;
    const float* Bb = bias ? (bias + y * bStrideY) : nullptr;
    float* Ob = O + y * oStrideY;

    {
        float4* sA4 = (float4*)sA;
#pragma unroll
        for (int i = 0; i < (R * K / 4) / N; i++) {
            int idx = t + i * N;
            float4 a;
            if (GEN) {
                // RBF on the fly: row p = row0 + r, col c
                const float GAM = 10.0f / 36.0f;
                int r = idx / (K / 4), c4 = idx % (K / 4);
                float dp = (float)(row0 + r) * (6.0f / (float)(P_TAB - 1));
                float d0 = dp - (float)(c4 * 4 + 0) * (6.0f / 63.0f);
                float d1 = dp - (float)(c4 * 4 + 1) * (6.0f / 63.0f);
                float d2 = dp - (float)(c4 * 4 + 2) * (6.0f / 63.0f);
                float d3 = dp - (float)(c4 * 4 + 3) * (6.0f / 63.0f);
                a.x = __expf(-GAM * d0 * d0);
                a.y = __expf(-GAM * d1 * d1);
                a.z = __expf(-GAM * d2 * d2);
                a.w = __expf(-GAM * d3 * d3);
            } else {
                a = ((const float4*)Ab)[idx];
                if (PREACT) {
                    a.x = silu_f(a.x); a.y = silu_f(a.y);
                    a.z = silu_f(a.z); a.w = silu_f(a.w);
                }
            }
            sA4[idx] = a;
        }
    }
    __syncthreads();

    float acc[R];
#pragma unroll
    for (int m = 0; m < R; m++) acc[m] = 0.0f;

#pragma unroll 4
    for (int k0 = 0; k0 < K; k0 += 4) {
        float w0 = __ldg(&Wb[(k0 + 0) * N + t]);
        float w1 = __ldg(&Wb[(k0 + 1) * N + t]);
        float w2 = __ldg(&Wb[(k0 + 2) * N + t]);
        float w3 = __ldg(&Wb[(k0 + 3) * N + t]);
#pragma unroll
        for (int m = 0; m < R; m++) {
            float4 a = *(const float4*)(sA + m * K + k0);
            acc[m] = fmaf(a.x, w0, fmaf(a.y, w1, fmaf(a.z, w2, fmaf(a.w, w3, acc[m]))));
        }
    }

    if (EPI == 0) {
#pragma unroll
        for (int m = 0; m < R; m++) Ob[(row0 + m) * N + t] = acc[m];
    } else if (EPI == 1) {
        float b = Bb[t];
#pragma unroll
        for (int m = 0; m < R; m++) Ob[(row0 + m) * N + t] = silu_f(acc[m] + b);
    } else {
        float b = Bb[t];
#pragma unroll
        for (int m = 0; m < R; m++) Ob[(row0 + m) * N + t] = acc[m] + b;
    }
}

// ---------------------------------------------------------------------------
// Aggregation: warp per dst node; lerp filter from (L1-resident) table,
// multiply with dequantized int16 hl[src], accumulate.
// ---------------------------------------------------------------------------

__global__ void __launch_bounds__(256) k_agg(const float* __restrict__ tab) {
    int warp = (blockIdx.x * blockDim.x + threadIdx.x) >> 5;
    int lane = threadIdx.x & 31;
    if (warp >= BN) return;
    int n = warp;
    int b0 = g_off[n], b1 = g_off[n + 1];
    const float4* tab4 = (const float4*)tab;
    const float USCALE = (float)(P_TAB - 1) / 6.0f;
    float4 acc = make_float4(0.f, 0.f, 0.f, 0.f);
    for (int k = b0; k < b1; k++) {
        int2 e = __ldg(&g_e2[k]);
        int s = e.x;
        float dv = __int_as_float(e.y);
        float u = dv * USCALE;
        int i0 = (int)u;
        if (i0 > P_TAB - 2) i0 = P_TAB - 2;
        float f = u - (float)i0;
        float4 t0 = tab4[i0 * 32 + lane];
        float4 t1 = tab4[(i0 + 1) * 32 + lane];
        short4 hq = __ldg((const short4*)&g_hlq[(long)s * HID + lane * 4]);
        float sc = __ldg(&g_hls[s]);
        float hx = sc * (float)hq.x;
        float hy = sc * (float)hq.y;
        float hz = sc * (float)hq.z;
        float hw = sc * (float)hq.w;
        acc.x = fmaf(fmaf(f, t1.x - t0.x, t0.x), hx, acc.x);
        acc.y = fmaf(fmaf(f, t1.y - t0.y, t0.y), hy, acc.y);
        acc.z = fmaf(fmaf(f, t1.z - t0.z, t0.z), hz, acc.z);
        acc.w = fmaf(fmaf(f, t1.w - t0.w, t0.w), hw, acc.w);
    }
    ((float4*)g_agg)[n * 32 + lane] = acc;
}

// ---------------------------------------------------------------------------
// Readout tail: e_atom = silu(x) @ ro_w2 + b2 summed per graph.
// ---------------------------------------------------------------------------

__global__ void __launch_bounds__(128) k_final(
    const float* __restrict__ w2, const float* __restrict__ b2,
    float* __restrict__ out)
{
    __shared__ float sw[64];
    __shared__ float red[128];
    int t = threadIdx.x, g = blockIdx.x;
    if (t < 64) sw[t] = w2[t];
    __syncthreads();
    int node = g * 128 + t;
    const float4* xr = (const float4*)(g_x + node * 64);
    float e = b2[0];
#pragma unroll
    for (int q = 0; q < 16; q++) {
        float4 v = xr[q];
        e += silu_f(v.x) * sw[q * 4 + 0] + silu_f(v.y) * sw[q * 4 + 1] +
             silu_f(v.z) * sw[q * 4 + 2] + silu_f(v.w) * sw[q * 4 + 3];
    }
    red[t] = e;
    __syncthreads();
    for (int s = 64; s > 0; s >>= 1) {
        if (t < s) red[t] += red[t + s];
        __syncthreads();
    }
    if (t == 0) out[g] = red[0];
}

// ---------------------------------------------------------------------------
// Launch
// ---------------------------------------------------------------------------

extern "C" void kernel_launch(void* const* d_in, const int* in_sizes, int n_in,
                              void* d_out, int out_size)
{
    const int*   Z        = (const int*)  d_in[0];
    const float* pos      = (const float*)d_in[1];
    const int*   ei       = (const int*)  d_in[2];
    const float* embed_w  = (const float*)d_in[3];
    const float* edge_w1  = (const float*)d_in[4];
    const float* edge_b1  = (const float*)d_in[5];
    const float* edge_w2  = (const float*)d_in[6];
    const float* edge_b2  = (const float*)d_in[7];
    const float* lin_in_w = (const float*)d_in[8];
    const float* node_w1  = (const float*)d_in[9];
    const float* node_b1  = (const float*)d_in[10];
    const float* node_w2  = (const float*)d_in[11];
    const float* node_b2  = (const float*)d_in[12];
    const float* ln_g     = (const float*)d_in[13];
    const float* ln_b     = (const float*)d_in[14];
    const float* ro_w1    = (const float*)d_in[15];
    const float* ro_b1    = (const float*)d_in[16];
    const float* ro_w2    = (const float*)d_in[17];
    const float* ro_b2    = (const float*)d_in[18];
    float* out = (float*)d_out;

    float *p_h, *p_agg, *p_tmp, *p_x, *p_htab, *p_tab;
    cudaGetSymbolAddress((void**)&p_h,    g_h);
    cudaGetSymbolAddress((void**)&p_agg,  g_agg);
    cudaGetSymbolAddress((void**)&p_tmp,  g_tmp);
    cudaGetSymbolAddress((void**)&p_x,    g_x);
    cudaGetSymbolAddress((void**)&p_htab, g_htab);
    cudaGetSymbolAddress((void**)&p_tab,  g_tab);

    const long TABY = (long)P_TAB * HID;

    // ---- setup ------------------------------------------------------------
    k_embed<<<BN * HID / 256, 256>>>(Z, embed_w);          // also zeroes g_deg
    k_dist_hist<<<E_TOT / 256, 256>>>(ei, pos);
    // lin_in for block 0 (quantized hl output)
    k_mma<2><<<BN / 64, 256>>>(p_h, lin_in_w, nullptr, nullptr);
    k_scan1<<<32, 256>>>();
    k_scan2<<<1, 32>>>();
    k_scan3<<<32, 256>>>();
    k_bucket<<<E_TOT / 256, 256>>>(ei);

    // ---- edge-filter lookup tables (RBF generated in-kernel) ---------------
    k_gemm<NRBF, HID, 1, 0, 1><<<dim3(P_TAB / 16, NBLK), HID>>>(
        nullptr, edge_w1, edge_b1, p_htab,
        0, (long)NRBF * HID, HID, TABY);
    k_gemm<HID, HID, 2, 0, 0><<<dim3(P_TAB / 16, NBLK), HID>>>(
        p_htab, edge_w2, edge_b2, p_tab,
        TABY, (long)HID * HID, HID, TABY);

    // ---- interaction blocks: agg -> w1 -> (w2+LN [+next lin_in quant]) -----
    for (int i = 0; i < NBLK; i++) {
        k_agg<<<BN / 8, 256>>>(p_tab + (size_t)i * TABY);
        k_mma<1><<<BN / 64, 256>>>(p_agg, node_w1 + (size_t)i * HID * HID,
                                   node_b1 + (size_t)i * HID, p_tmp);
        if (i < NBLK - 1) {
            k_f2<1><<<BN / 64, 256>>>(p_tmp, node_w2 + (size_t)i * HID * HID,
                                      node_b2 + (size_t)i * HID, p_h,
                                      ln_g + (size_t)i * HID, ln_b + (size_t)i * HID,
                                      lin_in_w + (size_t)(i + 1) * HID * HID);
        } else {
            k_f2<0><<<BN / 64, 256>>>(p_tmp, node_w2 + (size_t)i * HID * HID,
                                      node_b2 + (size_t)i * HID, p_h,
                                      ln_g + (size_t)i * HID, ln_b + (size_t)i * HID,
                                      nullptr);
        }
    }

    // ---- readout (silu fused into A staging) -------------------------------
    k_gemm<HID, 64, 2, 1, 0><<<BN / 16, 64>>>(
        p_h, ro_w1, ro_b1, p_x, 0, 0, 0, 0);
    k_final<<<64, 128>>>(ro_w2, ro_b2, out);
}